// round 13
// baseline (speedup 1.0000x reference)
#include <cuda_runtime.h>
#include <cuda_bf16.h>
#include <cstdint>
#include <cstddef>

// ---------------------------------------------------------------------------
// ContentContrastiveLoss, GB300 (sm_103 target: mma.sync only, no tcgen05).
// Round 13: ONE fused persistent kernel, overlap done right.
//   - 148 normalizer CTAs: cp.async ring (4x16KB, 64KB in flight each) streams
//     the 128MB input at DRAM rate; rows in progressive order r=iter*148+bid,
//     publishing 128-row groups early.
//   - 148 GEMM CTAs (co-resident, 2nd CTA per SM): band-ordered tile queue,
//     R10 GEMM internals (128x128, KC=64, 2-stage, 1 barrier/chunk).
//   - normalizers join the queue when done; 296th CTA finalizes + resets.
//   loss = ( sum_offdiag max(0.2-||ci-aj||,0)^2 + sum_i ||ci-ai||^2 ) / (2N)
// CS screen with HEAD=384: sim <= head_dot + rc_i*ra_j ; flag if > 0.97.
// ---------------------------------------------------------------------------

#define NROWS 2048
#define DIM   8192
#define HEAD  384
#define TILE  128
#define KC    64            // bf16 K elems per GEMM chunk (128B per row)
#define RSTR  144           // GEMM smem row stride BYTES (128 data + 16 pad)
#define GCHUNK (HEAD / KC)  // 6
#define FCAP  4096
#define NR    148           // normalizer CTAs
#define NGRID 296
#define NTILE ((NROWS / TILE) * (NROWS / TILE))   // 256
#define NGROUP (NROWS / TILE)                     // 16
#define BUFB  (TILE * RSTR)                       // 18432 B per GEMM buffer
#define NSLOT 16384         // normalize ring slot bytes (8KB C + 8KB A)

__device__ __nv_bfloat16 g_Ch[(size_t)NROWS * HEAD];
__device__ __nv_bfloat16 g_Ah[(size_t)NROWS * HEAD];
__device__ float  g_rc[NROWS];
__device__ float  g_ra[NROWS];
__device__ float  g_invC[NROWS];
__device__ float  g_invA[NROWS];
__device__ float  g_d2[NROWS];
__device__ int    g_groupdone[NGROUP];
__device__ int    g_tilectr;
__device__ int    g_done;
__device__ int    g_nflag;
__device__ int2   g_flags[FCAP];
__device__ double g_acc;

__device__ __forceinline__ uint32_t smem_u32(const void* p) {
    return (uint32_t)__cvta_generic_to_shared(p);
}
__device__ __forceinline__ void cp_async16(uint32_t dst, const void* src) {
    asm volatile("cp.async.cg.shared.global [%0], [%1], 16;" :: "r"(dst), "l"(src));
}
__device__ __forceinline__ void cp_commit() { asm volatile("cp.async.commit_group;"); }
template <int N>
__device__ __forceinline__ void cp_wait() {
    asm volatile("cp.async.wait_group %0;" :: "n"(N));
}
__device__ __forceinline__ void ldsm_x4(uint32_t (&r)[4], uint32_t addr) {
    asm volatile("ldmatrix.sync.aligned.m8n8.x4.shared.b16 {%0,%1,%2,%3}, [%4];"
                 : "=r"(r[0]), "=r"(r[1]), "=r"(r[2]), "=r"(r[3]) : "r"(addr));
}
__device__ __forceinline__ void mma_bf16(float (&d)[4], const uint32_t (&a)[4],
                                         const uint32_t b0, const uint32_t b1) {
    asm volatile(
        "mma.sync.aligned.m16n8k16.row.col.f32.bf16.bf16.f32 "
        "{%0,%1,%2,%3}, {%4,%5,%6,%7}, {%8,%9}, {%0,%1,%2,%3};"
        : "+f"(d[0]), "+f"(d[1]), "+f"(d[2]), "+f"(d[3])
        : "r"(a[0]), "r"(a[1]), "r"(a[2]), "r"(a[3]), "r"(b0), "r"(b1));
}
__device__ __forceinline__ float dot4(const float4 a, const float4 b) {
    return a.x * b.x + a.y * b.y + a.z * b.z + a.w * b.w;
}

// ---------------------------------------------------------------------------
__global__ void __launch_bounds__(256, 2) fused_kernel(
    const float* __restrict__ C, const float* __restrict__ A, float* out) {
    extern __shared__ __align__(16) unsigned char dsm[];
    // normalize phase: ring of 4 x 16KB slots in [0, 65536)
    // GEMM phase: A bufs [0,2*BUFB), B bufs [2*BUFB,4*BUFB), rcS/raS after
    unsigned char* sAb = dsm;
    unsigned char* sBb = dsm + 2 * BUFB;
    float* rcS = (float*)(dsm + 4 * BUFB);
    float* raS = rcS + TILE;
    __shared__ float red[8][5];
    __shared__ float redf[8];
    __shared__ double redd[8];
    __shared__ int sh_q, sh_last;

    const int bid  = blockIdx.x;
    const int tid  = threadIdx.x;
    const int wid  = tid >> 5;
    const int lane = tid & 31;
    const uint32_t dsm0 = smem_u32(dsm);

    // ==================== PHASE 1: normalize (bid < NR) ====================
    if (bid < NR) {
        const int nrows = (NROWS - bid + NR - 1) / NR;   // 13 or 14
        const int total = nrows * 4;                     // chunks (2048 elems)

        // issue chunk k into ring slot k&3 (per-thread: 2 C + 2 A float4)
        auto issue = [&](int k) {
            const int r = (k >> 2) * NR + bid;
            const int c = k & 3;
            const uint32_t slot = dsm0 + (uint32_t)(k & 3) * NSLOT;
            const float4* Cp = (const float4*)(C + (size_t)r * DIM) + c * 512;
            const float4* Ap = (const float4*)(A + (size_t)r * DIM) + c * 512;
            cp_async16(slot + tid * 16,              Cp + tid);
            cp_async16(slot + 4096 + tid * 16,       Cp + tid + 256);
            cp_async16(slot + 8192 + tid * 16,       Ap + tid);
            cp_async16(slot + 12288 + tid * 16,      Ap + tid + 256);
            cp_commit();
        };

#pragma unroll
        for (int k = 0; k < 4; k++) issue(k);   // prologue: row 0's 4 chunks

        float sC = 0.f, sA = 0.f, sD = 0.f, hC = 0.f, hA = 0.f;
        float4 cf0 = make_float4(0, 0, 0, 0), af0 = make_float4(0, 0, 0, 0);

        for (int k = 0; k < total; k++) {
            const int rem = total - 1 - k;
            if (rem >= 3)      cp_wait<3>();
            else if (rem == 2) cp_wait<2>();
            else if (rem == 1) cp_wait<1>();
            else               cp_wait<0>();

            const int c = k & 3;
            const unsigned char* slot = dsm + (size_t)(k & 3) * NSLOT;
            if (c == 0) { sC = sA = sD = hC = hA = 0.f; }

            const float4 c0 = *(const float4*)(slot + tid * 16);
            const float4 c1 = *(const float4*)(slot + 4096 + tid * 16);
            const float4 a0 = *(const float4*)(slot + 8192 + tid * 16);
            const float4 a1 = *(const float4*)(slot + 12288 + tid * 16);
            sC += dot4(c0, c0) + dot4(c1, c1);
            sA += dot4(a0, a0) + dot4(a1, a1);
            sD += dot4(c0, a0) + dot4(c1, a1);
            if (c == 0 && tid < (HEAD / 4)) {      // head = first 96 float4s
                cf0 = c0; af0 = a0;
                hC = dot4(c0, c0); hA = dot4(a0, a0);
            }

            if (k + 4 < total) issue(k + 4);       // keep 4 chunks in flight

            if (c == 3) {   // row complete: reduce + publish
                const int r = (k >> 2) * NR + bid;
                float v5[5] = {sC, sA, sD, hC, hA};
#pragma unroll
                for (int j = 0; j < 5; j++)
#pragma unroll
                    for (int o = 16; o; o >>= 1)
                        v5[j] += __shfl_down_sync(0xFFFFFFFFu, v5[j], o);
                if (lane == 0)
#pragma unroll
                    for (int j = 0; j < 5; j++) red[wid][j] = v5[j];
                __syncthreads();
                float tC = 0.f, tA = 0.f, tD = 0.f, tHC = 0.f, tHA = 0.f;
#pragma unroll
                for (int w = 0; w < 8; w++) {
                    tC += red[w][0]; tA += red[w][1]; tD += red[w][2];
                    tHC += red[w][3]; tHA += red[w][4];
                }
                const float invC = 1.0f / fmaxf(sqrtf(tC), 1e-12f);
                const float invA = 1.0f / fmaxf(sqrtf(tA), 1e-12f);

                if (tid < (HEAD / 4)) {
                    __nv_bfloat162 lo = __floats2bfloat162_rn(cf0.x * invC, cf0.y * invC);
                    __nv_bfloat162 hi = __floats2bfloat162_rn(cf0.z * invC, cf0.w * invC);
                    uint2 p;
                    p.x = *reinterpret_cast<uint32_t*>(&lo);
                    p.y = *reinterpret_cast<uint32_t*>(&hi);
                    ((uint2*)(g_Ch + (size_t)r * HEAD))[tid] = p;
                    lo = __floats2bfloat162_rn(af0.x * invA, af0.y * invA);
                    hi = __floats2bfloat162_rn(af0.z * invA, af0.w * invA);
                    p.x = *reinterpret_cast<uint32_t*>(&lo);
                    p.y = *reinterpret_cast<uint32_t*>(&hi);
                    ((uint2*)(g_Ah + (size_t)r * HEAD))[tid] = p;
                }
                if (tid == 0) {
                    const float sim = tD * invC * invA;
                    g_d2[r]   = fmaxf(2.0f - 2.0f * sim, 0.0f);
                    g_invC[r] = invC;
                    g_invA[r] = invA;
                    g_rc[r] = sqrtf(fmaxf(1.0f - tHC * invC * invC, 0.0f));
                    g_ra[r] = sqrtf(fmaxf(1.0f - tHA * invA * invA, 0.0f));
                }
                __threadfence();     // publish this row's data (all threads)
                __syncthreads();     // all writes done before counting
                if (tid == 0) atomicAdd(&g_groupdone[r >> 7], 1);
            }
        }
    }

    // ==================== PHASE 2: screen GEMM (all CTAs) ==================
    for (;;) {
        if (tid == 0) sh_q = atomicAdd(&g_tilectr, 1);
        __syncthreads();
        const int q = sh_q;
        if (q >= NTILE) break;

        // band-ordered decode: band = max(ti,tj)
        int band = (int)sqrtf((float)q);
        while ((band + 1) * (band + 1) <= q) band++;
        while (band * band > q) band--;
        const int pos = q - band * band;
        const int ti  = (pos <= band) ? band : (pos - band - 1);
        const int tj  = (pos <= band) ? pos  : band;

        if (tid == 0) {     // wait until both 128-row groups are published
            while (atomicAdd(&g_groupdone[ti], 0) < TILE) __nanosleep(128);
            while (atomicAdd(&g_groupdone[tj], 0) < TILE) __nanosleep(128);
        }
        __syncthreads();
        __threadfence();    // acquire published head data

        const __nv_bfloat16* __restrict__ Ab = g_Ch + (size_t)ti * TILE * HEAD;
        const __nv_bfloat16* __restrict__ Bb = g_Ah + (size_t)tj * TILE * HEAD;
        const int warp_m = wid & 3;
        const int warp_n = wid >> 2;

        const __nv_bfloat16* t_src[8];
        uint32_t t_dst[8];
#pragma unroll
        for (int t = 0; t < 8; t++) {
            const int task  = tid + t * 256;
            const int which = task >> 10;
            const int r     = (task >> 3) & 127;
            const int seg   = task & 7;
            t_src[t] = (which ? Bb : Ab) + (size_t)r * HEAD + seg * 8;
            t_dst[t] = smem_u32((which ? sBb : sAb) + r * RSTR + seg * 16);
        }
        uint32_t aAddr[2];
#pragma unroll
        for (int mf = 0; mf < 2; mf++) {
            const int r = warp_m * 32 + mf * 16 + (lane & 15);
            aAddr[mf] = smem_u32(sAb + r * RSTR + (lane >> 4) * 16);
        }
        uint32_t bAddr[4];
#pragma unroll
        for (int p = 0; p < 4; p++) {
            const int r = warp_n * 64 + p * 16 + (lane & 7) + ((lane >> 4) & 1) * 8;
            bAddr[p] = smem_u32(sBb + r * RSTR + ((lane >> 3) & 1) * 16);
        }

        float acc[2][8][4];
#pragma unroll
        for (int mf = 0; mf < 2; mf++)
#pragma unroll
            for (int nf = 0; nf < 8; nf++)
#pragma unroll
                for (int e = 0; e < 4; e++) acc[mf][nf][e] = 0.0f;

        if (tid < TILE) rcS[tid] = g_rc[ti * TILE + tid];
        else            raS[tid - TILE] = g_ra[tj * TILE + (tid - TILE)];

#pragma unroll
        for (int t = 0; t < 8; t++) cp_async16(t_dst[t], t_src[t]);
        cp_commit();

        for (int k0 = 0; k0 < GCHUNK; k0++) {
            cp_wait<0>();
            __syncthreads();
            if (k0 + 1 < GCHUNK) {
                const uint32_t nxt = (uint32_t)((k0 + 1) & 1) * BUFB;
                const int koff = (k0 + 1) * KC;
#pragma unroll
                for (int t = 0; t < 8; t++)
                    cp_async16(t_dst[t] + nxt, t_src[t] + koff);
                cp_commit();
            }
            const uint32_t cur = (uint32_t)(k0 & 1) * BUFB;
#pragma unroll
            for (int ks = 0; ks < 4; ks++) {
                uint32_t a[2][4];
#pragma unroll
                for (int mf = 0; mf < 2; mf++)
                    ldsm_x4(a[mf], aAddr[mf] + cur + ks * 32);
                uint32_t b[8][2];
#pragma unroll
                for (int p = 0; p < 4; p++) {
                    uint32_t r4[4];
                    ldsm_x4(r4, bAddr[p] + cur + ks * 32);
                    b[2 * p][0]     = r4[0];
                    b[2 * p][1]     = r4[1];
                    b[2 * p + 1][0] = r4[2];
                    b[2 * p + 1][1] = r4[3];
                }
#pragma unroll
                for (int mf = 0; mf < 2; mf++)
#pragma unroll
                    for (int nf = 0; nf < 8; nf++)
                        mma_bf16(acc[mf][nf], a[mf], b[nf][0], b[nf][1]);
            }
        }

        // screen: flag if CS bound can reach sim > 0.98 (0.01 slack)
#pragma unroll
        for (int mf = 0; mf < 2; mf++) {
#pragma unroll
            for (int nf = 0; nf < 8; nf++) {
#pragma unroll
                for (int e = 0; e < 4; e++) {
                    const int li = warp_m * 32 + mf * 16 + (lane >> 2) + (e >> 1) * 8;
                    const int lj = warp_n * 64 + nf * 8 + (lane & 3) * 2 + (e & 1);
                    const int gi = ti * TILE + li;
                    const int gj = tj * TILE + lj;
                    if (gi == gj) continue;
                    const float bound = acc[mf][nf][e] + rcS[li] * raS[lj];
                    if (bound > 0.97f) {
                        const int idx = atomicAdd(&g_nflag, 1);
                        if (idx < FCAP) g_flags[idx] = make_int2(gi, gj);
                    }
                }
            }
        }
        __syncthreads();   // all warps done with rcS/raS before next tile
    }

    // ==================== TERMINAL: last CTA finalizes =====================
    if (tid == 0) {
        __threadfence();
        sh_last = atomicAdd(&g_done, 1);
    }
    __syncthreads();
    if (sh_last != NGRID - 1) return;
    __threadfence();

    const int total = min(g_nflag, FCAP);
    for (int p = 0; p < total; p++) {   // expected: total == 0
        const int2 pr = g_flags[p];
        const float4* c = (const float4*)(C + (size_t)pr.x * DIM);
        const float4* a = (const float4*)(A + (size_t)pr.y * DIM);
        float s = 0.f;
        for (int i = tid; i < DIM / 4; i += 256) s += dot4(c[i], a[i]);
#pragma unroll
        for (int o = 16; o; o >>= 1) s += __shfl_down_sync(0xFFFFFFFFu, s, o);
        if (lane == 0) redf[wid] = s;
        __syncthreads();
        if (tid == 0) {
            float tot = 0.f;
#pragma unroll
            for (int w = 0; w < 8; w++) tot += redf[w];
            const float sim  = tot * g_invC[pr.x] * g_invA[pr.y];
            const float dist = sqrtf(fmaxf(2.0f - 2.0f * sim, 0.0f));
            const float diff = 0.2f - dist;
            if (diff > 0.0f) atomicAdd(&g_acc, (double)(diff * diff));
        }
        __syncthreads();
    }

    double ds = 0.0;
#pragma unroll
    for (int i = 0; i < 8; i++) ds += (double)g_d2[tid + i * 256];
#pragma unroll
    for (int o = 16; o; o >>= 1) ds += __shfl_down_sync(0xFFFFFFFFu, ds, o);
    if (lane == 0) redd[wid] = ds;
    __syncthreads();
    if (tid == 0) {
        double tot = atomicAdd(&g_acc, 0.0);
#pragma unroll
        for (int w = 0; w < 8; w++) tot += redd[w];
        out[0] = (float)(tot / (2.0 * (double)NROWS));
        g_acc     = 0.0;     // reset everything for the next graph replay
        g_nflag   = 0;
        g_tilectr = 0;
        g_done    = 0;
#pragma unroll
        for (int g = 0; g < NGROUP; g++) g_groupdone[g] = 0;
    }
}

extern "C" void kernel_launch(void* const* d_in, const int* in_sizes, int n_in,
                              void* d_out, int out_size) {
    (void)in_sizes; (void)n_in; (void)out_size;
    const float* C = (const float*)d_in[0];  // content_code
    const float* A = (const float*)d_in[1];  // audio_feature

    const int dyn_smem = 4 * BUFB + 2 * TILE * (int)sizeof(float);  // 74.75 KB
    cudaFuncSetAttribute(fused_kernel,
                         cudaFuncAttributeMaxDynamicSharedMemorySize, dyn_smem);
    fused_kernel<<<NGRID, 256, dyn_smem>>>(C, A, (float*)d_out);
}

// round 14
// speedup vs baseline: 1.3255x; 1.3255x over previous
#include <cuda_runtime.h>
#include <cuda_bf16.h>
#include <cstdint>
#include <cstddef>

// ---------------------------------------------------------------------------
// ContentContrastiveLoss, GB300 (sm_103 target: mma.sync only, no tcgen05).
// Round 14: R10 structure (best: 43.5us). New normalize: cp.async-staged
// row-pair into smem (register-free MLP=16/thread, 3 CTAs/SM) -> higher DRAM%.
//   loss = ( sum_offdiag max(0.2-||ci-aj||,0)^2 + sum_i ||ci-ai||^2 ) / (2N)
// CS screen with HEAD=384: sim <= head_dot + rc_i*ra_j ; flag if > 0.97.
// Exact fp32 diagonal during normalize. GEMM's last CTA: flags + finalize.
// ---------------------------------------------------------------------------

#define NROWS 2048
#define DIM   8192
#define HEAD  384
#define TILE  128
#define KC    64            // bf16 K elems per GEMM chunk (128B per row)
#define RSTR  144           // GEMM smem row stride BYTES (128 data + 16 pad)
#define NCHUNK (HEAD / KC)  // 6
#define FCAP  4096
#define NTILE ((NROWS / TILE) * (NROWS / TILE))   // 256
#define BUFB  (TILE * RSTR)                       // 18432 B per GEMM buffer

__device__ __nv_bfloat16 g_Ch[(size_t)NROWS * HEAD];
__device__ __nv_bfloat16 g_Ah[(size_t)NROWS * HEAD];
__device__ float  g_rc[NROWS];
__device__ float  g_ra[NROWS];
__device__ float  g_invC[NROWS];
__device__ float  g_invA[NROWS];
__device__ float  g_d2[NROWS];      // exact diagonal dist^2 per row
__device__ int    g_nflag;
__device__ int    g_done;
__device__ int2   g_flags[FCAP];
__device__ double g_acc;            // hinge accumulator (expected 0)

__device__ __forceinline__ uint32_t smem_u32(const void* p) {
    return (uint32_t)__cvta_generic_to_shared(p);
}
__device__ __forceinline__ void cp_async16(uint32_t dst, const void* src) {
    asm volatile("cp.async.cg.shared.global [%0], [%1], 16;" :: "r"(dst), "l"(src));
}
__device__ __forceinline__ void cp_commit() { asm volatile("cp.async.commit_group;"); }
template <int N>
__device__ __forceinline__ void cp_wait() {
    asm volatile("cp.async.wait_group %0;" :: "n"(N));
}
__device__ __forceinline__ void ldsm_x4(uint32_t (&r)[4], uint32_t addr) {
    asm volatile("ldmatrix.sync.aligned.m8n8.x4.shared.b16 {%0,%1,%2,%3}, [%4];"
                 : "=r"(r[0]), "=r"(r[1]), "=r"(r[2]), "=r"(r[3]) : "r"(addr));
}
__device__ __forceinline__ void mma_bf16(float (&d)[4], const uint32_t (&a)[4],
                                         const uint32_t b0, const uint32_t b1) {
    asm volatile(
        "mma.sync.aligned.m16n8k16.row.col.f32.bf16.bf16.f32 "
        "{%0,%1,%2,%3}, {%4,%5,%6,%7}, {%8,%9}, {%0,%1,%2,%3};"
        : "+f"(d[0]), "+f"(d[1]), "+f"(d[2]), "+f"(d[3])
        : "r"(a[0]), "r"(a[1]), "r"(a[2]), "r"(a[3]), "r"(b0), "r"(b1));
}
__device__ __forceinline__ float dot4(const float4 a, const float4 b) {
    return a.x * b.x + a.y * b.y + a.z * b.z + a.w * b.w;
}

// ---------------------------------------------------------------------------
// Kernel 1: per-row normalize via cp.async staging.
//   Block = one row-pair. 64KB dyn smem: C row [0,32K), A row [32K,64K).
//   16 cp.async/thread (zero register cost) -> full MLP; reduce from smem.
// ---------------------------------------------------------------------------
__global__ void __launch_bounds__(256) normalize_kernel(
    const float* __restrict__ C, const float* __restrict__ A) {
    extern __shared__ __align__(16) unsigned char nsm[];
    float4* sC4 = (float4*)nsm;                     // 2048 float4
    float4* sA4 = (float4*)(nsm + 32768);           // 2048 float4
    __shared__ float red[8][5];

    const int row = blockIdx.x;
    const int tid = threadIdx.x;
    const uint32_t sc = smem_u32(nsm);
    const uint32_t sa = sc + 32768;

    const float4* cs = (const float4*)(C + (size_t)row * DIM);
    const float4* as = (const float4*)(A + (size_t)row * DIM);

    // stage both rows: 16 cp.async per thread, no register pressure
#pragma unroll
    for (int i = 0; i < 8; i++)
        cp_async16(sc + (tid + i * 256) * 16, cs + tid + i * 256);
#pragma unroll
    for (int i = 0; i < 8; i++)
        cp_async16(sa + (tid + i * 256) * 16, as + tid + i * 256);
    cp_commit();
    cp_wait<0>();
    __syncthreads();

    float sCv = 0.f, sAv = 0.f, sDv = 0.f;
#pragma unroll
    for (int i = 0; i < 8; i++) {
        const float4 c = sC4[tid + i * 256];
        const float4 a = sA4[tid + i * 256];
        sCv += dot4(c, c);
        sAv += dot4(a, a);
        sDv += dot4(c, a);
    }
    const bool headT = tid < (HEAD / 4);   // head = first 96 float4s
    float hC = 0.f, hA = 0.f;
    float4 cf0 = make_float4(0, 0, 0, 0), af0 = make_float4(0, 0, 0, 0);
    if (headT) {
        cf0 = sC4[tid]; af0 = sA4[tid];
        hC = dot4(cf0, cf0); hA = dot4(af0, af0);
    }

    float v5[5] = {sCv, sAv, sDv, hC, hA};
#pragma unroll
    for (int j = 0; j < 5; j++)
#pragma unroll
        for (int o = 16; o; o >>= 1)
            v5[j] += __shfl_down_sync(0xFFFFFFFFu, v5[j], o);
    if ((tid & 31) == 0)
#pragma unroll
        for (int j = 0; j < 5; j++) red[tid >> 5][j] = v5[j];
    __syncthreads();
    float tC = 0.f, tA = 0.f, tD = 0.f, tHC = 0.f, tHA = 0.f;
#pragma unroll
    for (int w = 0; w < 8; w++) {
        tC += red[w][0]; tA += red[w][1]; tD += red[w][2];
        tHC += red[w][3]; tHA += red[w][4];
    }
    const float invC = 1.0f / fmaxf(sqrtf(tC), 1e-12f);
    const float invA = 1.0f / fmaxf(sqrtf(tA), 1e-12f);

    if (tid == 0) {
        const float sim = tD * invC * invA;
        g_d2[row]   = fmaxf(2.0f - 2.0f * sim, 0.0f);
        g_invC[row] = invC;
        g_invA[row] = invA;
        g_rc[row] = sqrtf(fmaxf(1.0f - tHC * invC * invC, 0.0f));
        g_ra[row] = sqrtf(fmaxf(1.0f - tHA * invA * invA, 0.0f));
    }

    if (headT) {
        __nv_bfloat162 lo = __floats2bfloat162_rn(cf0.x * invC, cf0.y * invC);
        __nv_bfloat162 hi = __floats2bfloat162_rn(cf0.z * invC, cf0.w * invC);
        uint2 p;
        p.x = *reinterpret_cast<uint32_t*>(&lo);
        p.y = *reinterpret_cast<uint32_t*>(&hi);
        ((uint2*)(g_Ch + (size_t)row * HEAD))[tid] = p;

        lo = __floats2bfloat162_rn(af0.x * invA, af0.y * invA);
        hi = __floats2bfloat162_rn(af0.z * invA, af0.w * invA);
        p.x = *reinterpret_cast<uint32_t*>(&lo);
        p.y = *reinterpret_cast<uint32_t*>(&hi);
        ((uint2*)(g_Ah + (size_t)row * HEAD))[tid] = p;
    }
}

// ---------------------------------------------------------------------------
// Kernel 2 (R10 verbatim): 128x128-tile bf16 HMMA screen GEMM, K=384, KC=64,
// 8 warps, ONE barrier per chunk: [wait][sync][issue k+1][compute k].
// Last-done CTA: exact fallback for flags, diag sum, finalize, reset.
// ---------------------------------------------------------------------------
__global__ void __launch_bounds__(256, 2) screen_gemm_kernel(
    const float* __restrict__ C, const float* __restrict__ A, float* out) {
    extern __shared__ __align__(16) unsigned char dsm[];
    unsigned char* sAb = dsm;
    unsigned char* sBb = dsm + 2 * BUFB;
    float* rcS = (float*)(dsm + 4 * BUFB);
    float* raS = rcS + TILE;
    __shared__ float redf[8];
    __shared__ double redd[8];
    __shared__ int sh_last;

    const int tid    = threadIdx.x;
    const int wid    = tid >> 5;
    const int lane   = tid & 31;
    const int warp_m = wid & 3;
    const int warp_n = wid >> 2;

    const int ti = blockIdx.y;
    const int tj = blockIdx.x;
    const __nv_bfloat16* __restrict__ Ab = g_Ch + (size_t)ti * TILE * HEAD;
    const __nv_bfloat16* __restrict__ Bb = g_Ah + (size_t)tj * TILE * HEAD;

    const __nv_bfloat16* t_src[8];
    uint32_t t_dst[8];
#pragma unroll
    for (int t = 0; t < 8; t++) {
        const int task  = tid + t * 256;
        const int which = task >> 10;
        const int r     = (task >> 3) & 127;
        const int seg   = task & 7;
        t_src[t] = (which ? Bb : Ab) + (size_t)r * HEAD + seg * 8;
        t_dst[t] = smem_u32((which ? sBb : sAb) + r * RSTR + seg * 16);
    }

    uint32_t aAddr[2];
#pragma unroll
    for (int mf = 0; mf < 2; mf++) {
        const int r = warp_m * 32 + mf * 16 + (lane & 15);
        aAddr[mf] = smem_u32(sAb + r * RSTR + (lane >> 4) * 16);
    }
    uint32_t bAddr[4];
#pragma unroll
    for (int p = 0; p < 4; p++) {
        const int r = warp_n * 64 + p * 16 + (lane & 7) + ((lane >> 4) & 1) * 8;
        bAddr[p] = smem_u32(sBb + r * RSTR + ((lane >> 3) & 1) * 16);
    }

    float acc[2][8][4];
#pragma unroll
    for (int mf = 0; mf < 2; mf++)
#pragma unroll
        for (int nf = 0; nf < 8; nf++)
#pragma unroll
            for (int e = 0; e < 4; e++) acc[mf][nf][e] = 0.0f;

    if (tid < TILE) rcS[tid] = g_rc[ti * TILE + tid];
    else            raS[tid - TILE] = g_ra[tj * TILE + (tid - TILE)];

#pragma unroll
    for (int t = 0; t < 8; t++) cp_async16(t_dst[t], t_src[t]);
    cp_commit();

    for (int k0 = 0; k0 < NCHUNK; k0++) {
        cp_wait<0>();
        __syncthreads();

        if (k0 + 1 < NCHUNK) {
            const uint32_t nxt = (uint32_t)((k0 + 1) & 1) * BUFB;
            const int koff = (k0 + 1) * KC;
#pragma unroll
            for (int t = 0; t < 8; t++) cp_async16(t_dst[t] + nxt, t_src[t] + koff);
            cp_commit();
        }

        const uint32_t cur = (uint32_t)(k0 & 1) * BUFB;
#pragma unroll
        for (int ks = 0; ks < 4; ks++) {
            uint32_t a[2][4];
#pragma unroll
            for (int mf = 0; mf < 2; mf++)
                ldsm_x4(a[mf], aAddr[mf] + cur + ks * 32);
            uint32_t b[8][2];
#pragma unroll
            for (int p = 0; p < 4; p++) {
                uint32_t r4[4];
                ldsm_x4(r4, bAddr[p] + cur + ks * 32);
                b[2 * p][0]     = r4[0];
                b[2 * p][1]     = r4[1];
                b[2 * p + 1][0] = r4[2];
                b[2 * p + 1][1] = r4[3];
            }
#pragma unroll
            for (int mf = 0; mf < 2; mf++)
#pragma unroll
                for (int nf = 0; nf < 8; nf++)
                    mma_bf16(acc[mf][nf], a[mf], b[nf][0], b[nf][1]);
        }
    }

    // ---- screen: flag if CS upper bound can reach sim > 0.98 (0.01 slack) ----
#pragma unroll
    for (int mf = 0; mf < 2; mf++) {
#pragma unroll
        for (int nf = 0; nf < 8; nf++) {
#pragma unroll
            for (int e = 0; e < 4; e++) {
                const int li = warp_m * 32 + mf * 16 + (lane >> 2) + (e >> 1) * 8;
                const int lj = warp_n * 64 + nf * 8 + (lane & 3) * 2 + (e & 1);
                const int gi = ti * TILE + li;
                const int gj = tj * TILE + lj;
                if (gi == gj) continue;  // diagonal handled exactly elsewhere
                const float bound = acc[mf][nf][e] + rcS[li] * raS[lj];
                if (bound > 0.97f) {
                    const int idx = atomicAdd(&g_nflag, 1);
                    if (idx < FCAP) g_flags[idx] = make_int2(gi, gj);
                }
            }
        }
    }

    // ---- terminal: last-done CTA -> fallback + diag sum + finalize + reset --
    if (tid == 0) {
        __threadfence();
        sh_last = atomicAdd(&g_done, 1);
    }
    __syncthreads();
    if (sh_last != NTILE - 1) return;
    __threadfence();  // acquire all other CTAs' flags / g_acc

    const int total = min(g_nflag, FCAP);
    for (int p = 0; p < total; p++) {   // expected: total == 0
        const int2 pr = g_flags[p];
        const float4* c = (const float4*)(C + (size_t)pr.x * DIM);
        const float4* a = (const float4*)(A + (size_t)pr.y * DIM);
        float s = 0.f;
        for (int i = tid; i < DIM / 4; i += 256) s += dot4(c[i], a[i]);
#pragma unroll
        for (int o = 16; o; o >>= 1) s += __shfl_down_sync(0xFFFFFFFFu, s, o);
        if (lane == 0) redf[wid] = s;
        __syncthreads();
        if (tid == 0) {
            float tot = 0.f;
#pragma unroll
            for (int w = 0; w < 8; w++) tot += redf[w];
            const float sim  = tot * g_invC[pr.x] * g_invA[pr.y];
            const float dist = sqrtf(fmaxf(2.0f - 2.0f * sim, 0.0f));
            const float diff = 0.2f - dist;
            if (diff > 0.0f) atomicAdd(&g_acc, (double)(diff * diff));
        }
        __syncthreads();
    }

    double ds = 0.0;
#pragma unroll
    for (int i = 0; i < 8; i++) ds += (double)g_d2[tid + i * 256];
#pragma unroll
    for (int o = 16; o; o >>= 1) ds += __shfl_down_sync(0xFFFFFFFFu, ds, o);
    if (lane == 0) redd[wid] = ds;
    __syncthreads();
    if (tid == 0) {
        double tot = atomicAdd(&g_acc, 0.0);
#pragma unroll
        for (int w = 0; w < 8; w++) tot += redd[w];
        out[0] = (float)(tot / (2.0 * (double)NROWS));
        g_acc   = 0.0;   // reset for next graph replay
        g_nflag = 0;
        g_done  = 0;
    }
}

extern "C" void kernel_launch(void* const* d_in, const int* in_sizes, int n_in,
                              void* d_out, int out_size) {
    (void)in_sizes; (void)n_in; (void)out_size;
    const float* C = (const float*)d_in[0];  // content_code
    const float* A = (const float*)d_in[1];  // audio_feature

    const int norm_smem = 65536;                                  // 64 KB
    const int gemm_smem = 4 * BUFB + 2 * TILE * (int)sizeof(float);
    cudaFuncSetAttribute(normalize_kernel,
                         cudaFuncAttributeMaxDynamicSharedMemorySize, norm_smem);
    cudaFuncSetAttribute(screen_gemm_kernel,
                         cudaFuncAttributeMaxDynamicSharedMemorySize, gemm_smem);

    normalize_kernel<<<NROWS, 256, norm_smem>>>(C, A);
    screen_gemm_kernel<<<dim3(NROWS / TILE, NROWS / TILE), 256, gemm_smem>>>(
        C, A, (float*)d_out);
}